// round 9
// baseline (speedup 1.0000x reference)
#include <cuda_runtime.h>
#include <cuda_pipeline.h>
#include <math_constants.h>

#define B_ 4
#define T_ 512
#define D_ 128
#define H_ 64
#define KP (H_ + 4)   // padded K row stride (conflict-free f4 phases)

#define SCORE_GRID (148*6)           // persistent: 6 CTAs/SM x 148 SMs
#define N_TILES    ((T_/8)*(T_/128)*B_)   // 64*4*4 = 1024

__device__ float g_Q[B_*T_*H_];
__device__ float g_K[B_*T_*H_];

__device__ __forceinline__ float tanh_fast(float x) {
    float y;
    asm("tanh.approx.f32 %0, %1;" : "=f"(y) : "f"(x));
    return y;
}

// ---------------------------------------------------------------------------
// Kernel 1: Q/K' prep. 8 t-rows/CTA, grid (T/8,B)=256. Full W staged once.
// ---------------------------------------------------------------------------
__global__ __launch_bounds__(256) void prep_kernel(
    const float* __restrict__ input, const float* __restrict__ demo,
    const float* __restrict__ Wt, const float* __restrict__ Wx,
    const float* __restrict__ Wd, const float* __restrict__ bh)
{
    extern __shared__ float dyn[];
    float* sx  = dyn;           // [8][128]
    float* sWt = dyn + 1024;    // [128][64]
    float* sWx = dyn + 9216;    // [128][64]

    const int b   = blockIdx.y;
    const int t0  = blockIdx.x * 8;
    const int tid = threadIdx.x;
    const int h   = tid & 63;
    const int rg  = tid >> 6;

    {
        const float4* gin = (const float4*)(input + (size_t)(b*T_ + t0)*D_);
        __pipeline_memcpy_async(&((float4*)sx)[tid], &gin[tid], 16);
        const float4* gt = (const float4*)Wt;
        const float4* gx = (const float4*)Wx;
        #pragma unroll
        for (int i = 0; i < 8; i++) {
            int idx = tid + 256*i;
            __pipeline_memcpy_async(&((float4*)sWt)[idx], &gt[idx], 16);
            __pipeline_memcpy_async(&((float4*)sWx)[idx], &gx[idx], 16);
        }
        __pipeline_commit();
    }

    float dd = bh[h];
    #pragma unroll
    for (int j = 0; j < 12; j++) dd = fmaf(demo[b*12 + j], Wd[j*H_ + h], dd);

    __pipeline_wait_prior(0);
    __syncthreads();

    float aq0=0.f, ak0=0.f, aq1=0.f, ak1=0.f;
    #pragma unroll 16
    for (int d = 0; d < D_; d++) {
        float wt = sWt[d*H_ + h];
        float wx = sWx[d*H_ + h];
        float x0 = sx[(rg    )*D_ + d];
        float x1 = sx[(rg + 4)*D_ + d];
        aq0 = fmaf(x0, wt, aq0);
        ak0 = fmaf(x0, wx, ak0);
        aq1 = fmaf(x1, wt, aq1);
        ak1 = fmaf(x1, wx, ak1);
    }

    const size_t o0 = (size_t)(b*T_ + t0 + rg    )*H_ + h;
    const size_t o1 = (size_t)(b*T_ + t0 + rg + 4)*H_ + h;
    g_Q[o0] = aq0;  g_K[o0] = ak0 + dd;
    g_Q[o1] = aq1;  g_K[o1] = ak1 + dd;
}

// ---------------------------------------------------------------------------
// Kernel 2: RAW scores, PERSISTENT. grid = 888 CTAs (6/SM), each striding
// over 1024 tiles of 8 t-rows x 128 s-cols. Tile body identical to R8.
// ---------------------------------------------------------------------------
__global__ __launch_bounds__(128, 6) void score_kernel(
    const float* __restrict__ Wa, const float* __restrict__ ba,
    float* __restrict__ out_e)
{
    __shared__ float sQ[8][H_];
    __shared__ float sWa[H_];
    __shared__ float sK[128][KP];

    const int tid = threadIdx.x;
    if (tid < H_/4) ((float4*)sWa)[tid] = ((const float4*)Wa)[tid];
    const float bav = ba[0];

    for (int tile = blockIdx.x; tile < N_TILES; tile += SCORE_GRID) {
        const int b  = tile >> 8;              // 256 tiles per batch
        const int s0 = ((tile >> 6) & 3) * 128;
        const int t0 = (tile & 63) * 8;

        {
            const float4* gq = (const float4*)(g_Q + (size_t)(b*T_ + t0)*H_);
            __pipeline_memcpy_async(&((float4*)sQ)[tid], &gq[tid], 16);
        }
        {
            const float4* kp = (const float4*)(g_K + (size_t)(b*T_ + s0)*H_);
            const int j  = tid & 15;
            const int r0 = tid >> 4;
            #pragma unroll
            for (int i = 0; i < 16; i++) {
                int r = r0 + 8*i;
                __pipeline_memcpy_async(&sK[r][4*j], &kp[(size_t)r*16 + j], 16);
            }
        }
        __pipeline_commit();
        __pipeline_wait_prior(0);
        __syncthreads();

        const int s = tid;
        float acc[8] = {0.f,0.f,0.f,0.f,0.f,0.f,0.f,0.f};

        #pragma unroll
        for (int h4 = 0; h4 < H_/4; h4++) {
            float4 k = *(const float4*)&sK[s][4*h4];
            float4 w = ((const float4*)sWa)[h4];
            #pragma unroll
            for (int t = 0; t < 8; t++) {
                float4 q = ((const float4*)sQ[t])[h4];
                acc[t] = fmaf(w.x, tanh_fast(q.x + k.x), acc[t]);
                acc[t] = fmaf(w.y, tanh_fast(q.y + k.y), acc[t]);
                acc[t] = fmaf(w.z, tanh_fast(q.z + k.z), acc[t]);
                acc[t] = fmaf(w.w, tanh_fast(q.w + k.w), acc[t]);
            }
        }

        float* ge = out_e + ((size_t)(b*T_ + t0))*T_ + s0 + s;
        #pragma unroll
        for (int t = 0; t < 8; t++) ge[(size_t)t*T_] = acc[t] + bav;

        __syncthreads();   // all reads of sQ/sK done before next tile's loads
    }
}

// ---------------------------------------------------------------------------
// Kernel 3: fused softmax + causally-truncated v (R8 version, unchanged).
// ---------------------------------------------------------------------------
__global__ __launch_bounds__(256) void sv_kernel(
    const float* __restrict__ input, float* __restrict__ out_e,
    float* __restrict__ out_v)
{
    __shared__ float sP[8][T_];        // 16 KB
    __shared__ float sIn[32][D_];      // 16 KB

    const int b    = blockIdx.y;
    const int t0   = ((int)gridDim.x - 1 - (int)blockIdx.x) * 8;  // heavy first
    const int tid  = threadIdx.x;
    const int w    = tid >> 5;
    const int lane = tid & 31;
    const int t    = t0 + w;

    // ---- softmax over raw row (max over FULL row, exp, THEN mask s<=t) ----
    {
        float* ge = out_e + ((size_t)(b*T_ + t))*T_;
        float vals[T_/32];
        float m = -CUDART_INF_F;
        #pragma unroll
        for (int i = 0; i < T_/32; i++) {
            vals[i] = ge[lane + 32*i];
            m = fmaxf(m, vals[i]);
        }
        #pragma unroll
        for (int off = 16; off; off >>= 1) m = fmaxf(m, __shfl_xor_sync(0xffffffffu, m, off));
        float sum = 0.f;
        #pragma unroll
        for (int i = 0; i < T_/32; i++) {
            int s = lane + 32*i;
            float e = __expf(vals[i] - m);
            if (s > t) e = 0.f;          // causal mask AFTER exp
            vals[i] = e;
            sum += e;
        }
        #pragma unroll
        for (int off = 16; off; off >>= 1) sum += __shfl_xor_sync(0xffffffffu, sum, off);
        float inv = 1.f / (sum + 1e-7f);
        #pragma unroll
        for (int i = 0; i < T_/32; i++) {
            int s = lane + 32*i;
            float p = vals[i] * inv;
            ge[s]    = p;
            sP[w][s] = p;
        }
        __syncwarp();
    }

    // ---- v phase: only chunks containing s <= t0+7 (P is 0 beyond) ----
    const int nc = t0/32 + 1;          // 1..16 chunks
    float4 acc = make_float4(0.f,0.f,0.f,0.f);
    for (int c = 0; c < nc; c++) {
        __syncthreads();
        {
            const float4* gin = (const float4*)(input + (size_t)(b*T_ + c*32)*D_);
            #pragma unroll
            for (int i = 0; i < 4; i++) ((float4*)sIn)[tid + 256*i] = gin[tid + 256*i];
        }
        __syncthreads();
        #pragma unroll
        for (int s = 0; s < 32; s++) {
            float p = sP[w][c*32 + s];
            float4 x = ((const float4*)sIn[s])[lane];
            acc.x = fmaf(p, x.x, acc.x);
            acc.y = fmaf(p, x.y, acc.y);
            acc.z = fmaf(p, x.z, acc.z);
            acc.w = fmaf(p, x.w, acc.w);
        }
    }
    ((float4*)(out_v + (size_t)(b*T_ + t)*D_))[lane] = acc;
}

// ---------------------------------------------------------------------------
extern "C" void kernel_launch(void* const* d_in, const int* in_sizes, int n_in,
                              void* d_out, int out_size)
{
    const float* input = (const float*)d_in[0];
    const float* demo  = (const float*)d_in[1];
    const float* Wt    = (const float*)d_in[2];
    const float* Wx    = (const float*)d_in[3];
    const float* Wd    = (const float*)d_in[4];
    const float* bh    = (const float*)d_in[5];
    const float* Wa    = (const float*)d_in[6];
    const float* ba    = (const float*)d_in[7];

    float* out_v = (float*)d_out;                   // [B,T,D]
    float* out_e = out_v + (size_t)B_ * T_ * D_;    // [B,T,T]

    static int smem_set = 0;
    const int prep_smem = (1024 + 2*8192) * 4;
    if (!smem_set) {
        cudaFuncSetAttribute(prep_kernel, cudaFuncAttributeMaxDynamicSharedMemorySize, prep_smem);
        smem_set = 1;
    }

    dim3 g1(T_/8, B_);
    prep_kernel<<<g1, 256, prep_smem>>>(input, demo, Wt, Wx, Wd, bh);

    score_kernel<<<SCORE_GRID, 128>>>(Wa, ba, out_e);

    dim3 g3(T_/8, B_);
    sv_kernel<<<g3, 256>>>(input, out_e, out_v);
}

// round 10
// speedup vs baseline: 1.0814x; 1.0814x over previous
#include <cuda_runtime.h>
#include <cuda_pipeline.h>
#include <math_constants.h>

#define B_ 4
#define T_ 512
#define D_ 128
#define H_ 64
#define KP (H_ + 4)   // padded K row stride (conflict-free f4 phases)

#define N_TRI_TILES 160   // lower-triangular (t0-tile i, s0-tile j): j*128 <= i*8+7

__device__ float g_Q[B_*T_*H_];
__device__ float g_K[B_*T_*H_];

__device__ __forceinline__ float tanh_fast(float x) {
    float y;
    asm("tanh.approx.f32 %0, %1;" : "=f"(y) : "f"(x));
    return y;
}

// ---------------------------------------------------------------------------
// Kernel 1: Q/K' prep. 4 t-rows/CTA, grid (T/4,B)=512 CTAs (~3.5/SM).
// Full W staged once via cp.async; one wait, one sync, pure LDS+FFMA loop.
// ---------------------------------------------------------------------------
__global__ __launch_bounds__(256) void prep_kernel(
    const float* __restrict__ input, const float* __restrict__ demo,
    const float* __restrict__ Wt, const float* __restrict__ Wx,
    const float* __restrict__ Wd, const float* __restrict__ bh)
{
    extern __shared__ float dyn[];
    float* sx  = dyn;          // [4][128]  = 512 floats
    float* sWt = dyn + 512;    // [128][64]
    float* sWx = dyn + 8704;   // [128][64]

    const int b   = blockIdx.y;
    const int t0  = blockIdx.x * 4;
    const int tid = threadIdx.x;
    const int h   = tid & 63;
    const int rg  = tid >> 6;          // 0..3 -> this thread's row

    {
        if (tid < 128) {
            const float4* gin = (const float4*)(input + (size_t)(b*T_ + t0)*D_);
            __pipeline_memcpy_async(&((float4*)sx)[tid], &gin[tid], 16);
        }
        const float4* gt = (const float4*)Wt;
        const float4* gx = (const float4*)Wx;
        #pragma unroll
        for (int i = 0; i < 8; i++) {
            int idx = tid + 256*i;
            __pipeline_memcpy_async(&((float4*)sWt)[idx], &gt[idx], 16);
            __pipeline_memcpy_async(&((float4*)sWx)[idx], &gx[idx], 16);
        }
        __pipeline_commit();
    }

    float dd = bh[h];
    #pragma unroll
    for (int j = 0; j < 12; j++) dd = fmaf(demo[b*12 + j], Wd[j*H_ + h], dd);

    __pipeline_wait_prior(0);
    __syncthreads();

    float aq = 0.f, ak = 0.f;
    #pragma unroll 16
    for (int d = 0; d < D_; d++) {
        float x = sx[rg*D_ + d];
        aq = fmaf(x, sWt[d*H_ + h], aq);
        ak = fmaf(x, sWx[d*H_ + h], ak);
    }

    const size_t o = (size_t)(b*T_ + t0 + rg)*H_ + h;
    g_Q[o] = aq;
    g_K[o] = ak + dd;
}

// ---------------------------------------------------------------------------
// Kernel 2: RAW scores, LOWER-TRIANGULAR tiles only (s>t never needed:
// softmax shift-invariance makes the pre-mask row max irrelevant up to
// eps*exp(dm)/S' <= ~1e-5). CTA = 8 t-rows x 128 s-cols, 128 threads.
// grid (160, B) = 640 CTAs = single wave at 6 CTAs/SM.
// ---------------------------------------------------------------------------
__global__ __launch_bounds__(128, 6) void score_kernel(
    const float* __restrict__ Wa, const float* __restrict__ ba,
    float* __restrict__ out_e)
{
    __shared__ float sQ[8][H_];
    __shared__ float sWa[H_];
    __shared__ float sK[128][KP];

    const int b   = blockIdx.y;
    const int k   = blockIdx.x;        // 0..159 -> (i,j) lower-tri tile
    int i, j;
    if (k < 64)       { j = 0; i = k; }
    else if (k < 112) { j = 1; i = 16 + (k - 64); }
    else if (k < 144) { j = 2; i = 32 + (k - 112); }
    else              { j = 3; i = 48 + (k - 144); }
    const int t0 = i * 8;
    const int s0 = j * 128;
    const int tid = threadIdx.x;

    {
        const float4* gq = (const float4*)(g_Q + (size_t)(b*T_ + t0)*H_);
        ((float4*)sQ)[tid] = gq[tid];
        if (tid < H_/4) ((float4*)sWa)[tid] = ((const float4*)Wa)[tid];
    }
    {
        const float4* kp = (const float4*)(g_K + (size_t)(b*T_ + s0)*H_);
        const int jj = tid & 15;
        const int r0 = tid >> 4;
        #pragma unroll
        for (int ii = 0; ii < 16; ii++) {
            int r = r0 + 8*ii;
            __pipeline_memcpy_async(&sK[r][4*jj], &kp[(size_t)r*16 + jj], 16);
        }
        __pipeline_commit();
    }
    __pipeline_wait_prior(0);
    __syncthreads();

    const int s = tid;
    float acc[8] = {0.f,0.f,0.f,0.f,0.f,0.f,0.f,0.f};

    #pragma unroll
    for (int h4 = 0; h4 < H_/4; h4++) {
        float4 kk = *(const float4*)&sK[s][4*h4];
        float4 w  = ((const float4*)sWa)[h4];
        #pragma unroll
        for (int t = 0; t < 8; t++) {
            float4 q = ((const float4*)sQ[t])[h4];
            acc[t] = fmaf(w.x, tanh_fast(q.x + kk.x), acc[t]);
            acc[t] = fmaf(w.y, tanh_fast(q.y + kk.y), acc[t]);
            acc[t] = fmaf(w.z, tanh_fast(q.z + kk.z), acc[t]);
            acc[t] = fmaf(w.w, tanh_fast(q.w + kk.w), acc[t]);
        }
    }

    const float bav = ba[0];
    float* ge = out_e + ((size_t)(b*T_ + t0))*T_ + s0 + s;
    #pragma unroll
    for (int t = 0; t < 8; t++) ge[(size_t)t*T_] = acc[t] + bav;
}

// ---------------------------------------------------------------------------
// Kernel 3: fused softmax + causally-truncated v. Warp per t-row, 8 rows/CTA,
// 256 threads. Softmax reads ONLY s<=t (rest -inf -> exp 0), max/sum over
// causal part (valid: softmax shift-invariance, see score kernel comment).
// Writes p for ALL s (0 beyond t) so out_e is fully initialized.
// ---------------------------------------------------------------------------
__global__ __launch_bounds__(256) void sv_kernel(
    const float* __restrict__ input, float* __restrict__ out_e,
    float* __restrict__ out_v)
{
    __shared__ float sP[8][T_];        // 16 KB
    __shared__ float sIn[32][D_];      // 16 KB

    const int b    = blockIdx.y;
    const int t0   = ((int)gridDim.x - 1 - (int)blockIdx.x) * 8;  // heavy first
    const int tid  = threadIdx.x;
    const int w    = tid >> 5;
    const int lane = tid & 31;
    const int t    = t0 + w;

    // ---- causal softmax ----
    {
        float* ge = out_e + ((size_t)(b*T_ + t))*T_;
        float vals[T_/32];
        float m = -CUDART_INF_F;
        #pragma unroll
        for (int i = 0; i < T_/32; i++) {
            int s = lane + 32*i;
            vals[i] = (s <= t) ? ge[s] : -CUDART_INF_F;
            m = fmaxf(m, vals[i]);
        }
        #pragma unroll
        for (int off = 16; off; off >>= 1) m = fmaxf(m, __shfl_xor_sync(0xffffffffu, m, off));
        float sum = 0.f;
        #pragma unroll
        for (int i = 0; i < T_/32; i++) {
            float e = __expf(vals[i] - m);   // -inf -> 0
            vals[i] = e;
            sum += e;
        }
        #pragma unroll
        for (int off = 16; off; off >>= 1) sum += __shfl_xor_sync(0xffffffffu, sum, off);
        float inv = 1.f / (sum + 1e-7f);
        #pragma unroll
        for (int i = 0; i < T_/32; i++) {
            int s = lane + 32*i;
            float p = vals[i] * inv;
            ge[s]    = p;     // 0 for s>t
            sP[w][s] = p;
        }
        __syncwarp();
    }

    // ---- v phase: only chunks containing s <= t0+7 (P is 0 beyond) ----
    const int nc = t0/32 + 1;          // 1..16 chunks
    float4 acc = make_float4(0.f,0.f,0.f,0.f);
    for (int c = 0; c < nc; c++) {
        __syncthreads();
        {
            const float4* gin = (const float4*)(input + (size_t)(b*T_ + c*32)*D_);
            #pragma unroll
            for (int i = 0; i < 4; i++) ((float4*)sIn)[tid + 256*i] = gin[tid + 256*i];
        }
        __syncthreads();
        #pragma unroll
        for (int s = 0; s < 32; s++) {
            float p = sP[w][c*32 + s];
            float4 x = ((const float4*)sIn[s])[lane];
            acc.x = fmaf(p, x.x, acc.x);
            acc.y = fmaf(p, x.y, acc.y);
            acc.z = fmaf(p, x.z, acc.z);
            acc.w = fmaf(p, x.w, acc.w);
        }
    }
    ((float4*)(out_v + (size_t)(b*T_ + t)*D_))[lane] = acc;
}

// ---------------------------------------------------------------------------
extern "C" void kernel_launch(void* const* d_in, const int* in_sizes, int n_in,
                              void* d_out, int out_size)
{
    const float* input = (const float*)d_in[0];
    const float* demo  = (const float*)d_in[1];
    const float* Wt    = (const float*)d_in[2];
    const float* Wx    = (const float*)d_in[3];
    const float* Wd    = (const float*)d_in[4];
    const float* bh    = (const float*)d_in[5];
    const float* Wa    = (const float*)d_in[6];
    const float* ba    = (const float*)d_in[7];

    float* out_v = (float*)d_out;                   // [B,T,D]
    float* out_e = out_v + (size_t)B_ * T_ * D_;    // [B,T,T]

    static int smem_set = 0;
    const int prep_smem = (512 + 2*8192) * 4;       // 67,584 B
    if (!smem_set) {
        cudaFuncSetAttribute(prep_kernel, cudaFuncAttributeMaxDynamicSharedMemorySize, prep_smem);
        smem_set = 1;
    }

    dim3 g1(T_/4, B_);
    prep_kernel<<<g1, 256, prep_smem>>>(input, demo, Wt, Wx, Wd, bh);

    dim3 g2(N_TRI_TILES, B_);
    score_kernel<<<g2, 128>>>(Wa, ba, out_e);

    dim3 g3(T_/8, B_);
    sv_kernel<<<g3, 256>>>(input, out_e, out_v);
}

// round 11
// speedup vs baseline: 1.1292x; 1.0442x over previous
#include <cuda_runtime.h>
#include <cuda_pipeline.h>
#include <math_constants.h>

#define B_ 4
#define T_ 512
#define D_ 128
#define H_ 64
#define KP (H_ + 4)   // padded K row stride (conflict-free f4 phases)

__device__ float g_Q[B_*T_*H_];
__device__ float g_K[B_*T_*H_];

__device__ __forceinline__ float tanh_fast(float x) {
    float y;
    asm("tanh.approx.f32 %0, %1;" : "=f"(y) : "f"(x));
    return y;
}

// ---------------------------------------------------------------------------
// Kernel 1: Q/K' prep (R8 version). 8 t-rows/CTA, grid (T/8,B)=256.
// ---------------------------------------------------------------------------
__global__ __launch_bounds__(256) void prep_kernel(
    const float* __restrict__ input, const float* __restrict__ demo,
    const float* __restrict__ Wt, const float* __restrict__ Wx,
    const float* __restrict__ Wd, const float* __restrict__ bh)
{
    extern __shared__ float dyn[];
    float* sx  = dyn;           // [8][128]
    float* sWt = dyn + 1024;    // [128][64]
    float* sWx = dyn + 9216;    // [128][64]

    const int b   = blockIdx.y;
    const int t0  = blockIdx.x * 8;
    const int tid = threadIdx.x;
    const int h   = tid & 63;
    const int rg  = tid >> 6;

    {
        const float4* gin = (const float4*)(input + (size_t)(b*T_ + t0)*D_);
        __pipeline_memcpy_async(&((float4*)sx)[tid], &gin[tid], 16);
        const float4* gt = (const float4*)Wt;
        const float4* gx = (const float4*)Wx;
        #pragma unroll
        for (int i = 0; i < 8; i++) {
            int idx = tid + 256*i;
            __pipeline_memcpy_async(&((float4*)sWt)[idx], &gt[idx], 16);
            __pipeline_memcpy_async(&((float4*)sWx)[idx], &gx[idx], 16);
        }
        __pipeline_commit();
    }

    float dd = bh[h];
    #pragma unroll
    for (int j = 0; j < 12; j++) dd = fmaf(demo[b*12 + j], Wd[j*H_ + h], dd);

    __pipeline_wait_prior(0);
    __syncthreads();

    float aq0=0.f, ak0=0.f, aq1=0.f, ak1=0.f;
    #pragma unroll 16
    for (int d = 0; d < D_; d++) {
        float wt = sWt[d*H_ + h];
        float wx = sWx[d*H_ + h];
        float x0 = sx[(rg    )*D_ + d];
        float x1 = sx[(rg + 4)*D_ + d];
        aq0 = fmaf(x0, wt, aq0);
        ak0 = fmaf(x0, wx, ak0);
        aq1 = fmaf(x1, wt, aq1);
        ak1 = fmaf(x1, wx, ak1);
    }

    const size_t o0 = (size_t)(b*T_ + t0 + rg    )*H_ + h;
    const size_t o1 = (size_t)(b*T_ + t0 + rg + 4)*H_ + h;
    g_Q[o0] = aq0;  g_K[o0] = ak0 + dd;
    g_Q[o1] = aq1;  g_K[o1] = ak1 + dd;
}

// ---------------------------------------------------------------------------
// Kernel 2: FUSED strip kernel. CTA per (b, 8-row t-strip i), 256 threads.
// Phase 1: causal scores in 64-s chunks (nk = i/8+1) -> sSc (smem)
// Phase 2: causal softmax in place, P -> out_e (zeros above diagonal)
// Phase 3: v = P @ input, truncated, input staged in reused K buffer.
// Heavy strips launch first (i = 63 - blockIdx.x).
// ---------------------------------------------------------------------------
__global__ __launch_bounds__(256, 5) void strip_kernel(
    const float* __restrict__ input,
    const float* __restrict__ Wa, const float* __restrict__ ba,
    float* __restrict__ out_e, float* __restrict__ out_v)
{
    __shared__ float sQ[8][H_];        // 2 KB
    __shared__ float sWa[H_];
    __shared__ float sK[64][KP];       // 17.4 KB (reused as input stage in v)
    __shared__ float sSc[8][T_];       // 16 KB

    const int b    = blockIdx.y;
    const int i_s  = 63 - (int)blockIdx.x;     // heavy first
    const int t0   = i_s * 8;
    const int tid  = threadIdx.x;

    {   // Q strip: 8 rows = 128 f4 (threads 0..127), Wa by threads 128+
        if (tid < 128) {
            const float4* gq = (const float4*)(g_Q + (size_t)(b*T_ + t0)*H_);
            ((float4*)sQ)[tid] = gq[tid];
        } else if (tid < 128 + H_/4) {
            ((float4*)sWa)[tid - 128] = ((const float4*)Wa)[tid - 128];
        }
    }
    const float bav = ba[0];

    // ---- Phase 1: scores for s-chunks 0..nk-1 (64 rows each) ----
    const int nk = i_s/8 + 1;
    const int sl = tid & 63;
    const int tg = tid >> 6;       // rows tg and tg+4
    const int j4 = tid & 15;       // f4 col for K load
    const int r4 = tid >> 4;       // 16 rows per pass

    for (int c = 0; c < nk; c++) {
        __syncthreads();           // sK free (covers sQ/sWa on first iter)
        {
            const float4* kp = (const float4*)(g_K + (size_t)(b*T_ + c*64)*H_);
            #pragma unroll
            for (int ii = 0; ii < 4; ii++) {
                int r = r4 + 16*ii;
                __pipeline_memcpy_async(&sK[r][4*j4], &kp[(size_t)r*16 + j4], 16);
            }
            __pipeline_commit();
        }
        __pipeline_wait_prior(0);
        __syncthreads();

        float a0=0.f,a1=0.f,a2=0.f,a3=0.f,b0=0.f,b1=0.f,b2=0.f,b3=0.f;
        #pragma unroll
        for (int h4 = 0; h4 < H_/4; h4++) {
            float4 k  = *(const float4*)&sK[sl][4*h4];
            float4 w  = ((const float4*)sWa)[h4];
            float4 q0 = ((const float4*)sQ[tg])[h4];
            float4 q1 = ((const float4*)sQ[tg+4])[h4];
            a0 = fmaf(w.x, tanh_fast(q0.x + k.x), a0);
            a1 = fmaf(w.y, tanh_fast(q0.y + k.y), a1);
            a2 = fmaf(w.z, tanh_fast(q0.z + k.z), a2);
            a3 = fmaf(w.w, tanh_fast(q0.w + k.w), a3);
            b0 = fmaf(w.x, tanh_fast(q1.x + k.x), b0);
            b1 = fmaf(w.y, tanh_fast(q1.y + k.y), b1);
            b2 = fmaf(w.z, tanh_fast(q1.z + k.z), b2);
            b3 = fmaf(w.w, tanh_fast(q1.w + k.w), b3);
        }
        sSc[tg  ][c*64 + sl] = bav + ((a0 + a1) + (a2 + a3));
        sSc[tg+4][c*64 + sl] = bav + ((b0 + b1) + (b2 + b3));
    }
    __syncthreads();

    // ---- Phase 2: causal softmax per warp-row, P -> sSc and out_e ----
    const int w    = tid >> 5;
    const int lane = tid & 31;
    const int t    = t0 + w;
    {
        float vals[T_/32];
        float m = -CUDART_INF_F;
        #pragma unroll
        for (int i = 0; i < T_/32; i++) {
            int s = lane + 32*i;
            vals[i] = (s <= t) ? sSc[w][s] : -CUDART_INF_F;
            m = fmaxf(m, vals[i]);
        }
        #pragma unroll
        for (int off = 16; off; off >>= 1) m = fmaxf(m, __shfl_xor_sync(0xffffffffu, m, off));
        float sum = 0.f;
        #pragma unroll
        for (int i = 0; i < T_/32; i++) {
            float e = __expf(vals[i] - m);   // -inf -> 0
            vals[i] = e;
            sum += e;
        }
        #pragma unroll
        for (int off = 16; off; off >>= 1) sum += __shfl_xor_sync(0xffffffffu, sum, off);
        float inv = 1.f / (sum + 1e-7f);
        float* ge = out_e + ((size_t)(b*T_ + t))*T_;
        #pragma unroll
        for (int i = 0; i < T_/32; i++) {
            int s = lane + 32*i;
            float p = vals[i] * inv;         // 0 for s>t
            ge[s]     = p;
            sSc[w][s] = p;
        }
    }

    // ---- Phase 3: v = P @ input over causal chunks, input staged in sK ----
    const int nc = t0/32 + 1;
    float* sIn = &sK[0][0];        // 32 x 128 floats = 16 KB (fits in sK)
    float4 acc = make_float4(0.f,0.f,0.f,0.f);
    for (int c = 0; c < nc; c++) {
        __syncthreads();
        {
            const float4* gin = (const float4*)(input + (size_t)(b*T_ + c*32)*D_);
            #pragma unroll
            for (int ii = 0; ii < 4; ii++) ((float4*)sIn)[tid + 256*ii] = gin[tid + 256*ii];
        }
        __syncthreads();
        #pragma unroll
        for (int s = 0; s < 32; s++) {
            float p = sSc[w][c*32 + s];
            float4 x = ((const float4*)(sIn + s*D_))[lane];
            acc.x = fmaf(p, x.x, acc.x);
            acc.y = fmaf(p, x.y, acc.y);
            acc.z = fmaf(p, x.z, acc.z);
            acc.w = fmaf(p, x.w, acc.w);
        }
    }
    ((float4*)(out_v + (size_t)(b*T_ + t)*D_))[lane] = acc;
}

// ---------------------------------------------------------------------------
extern "C" void kernel_launch(void* const* d_in, const int* in_sizes, int n_in,
                              void* d_out, int out_size)
{
    const float* input = (const float*)d_in[0];
    const float* demo  = (const float*)d_in[1];
    const float* Wt    = (const float*)d_in[2];
    const float* Wx    = (const float*)d_in[3];
    const float* Wd    = (const float*)d_in[4];
    const float* bh    = (const float*)d_in[5];
    const float* Wa    = (const float*)d_in[6];
    const float* ba    = (const float*)d_in[7];

    float* out_v = (float*)d_out;                   // [B,T,D]
    float* out_e = out_v + (size_t)B_ * T_ * D_;    // [B,T,T]

    static int smem_set = 0;
    const int prep_smem = (1024 + 2*8192) * 4;
    if (!smem_set) {
        cudaFuncSetAttribute(prep_kernel, cudaFuncAttributeMaxDynamicSharedMemorySize, prep_smem);
        smem_set = 1;
    }

    dim3 g1(T_/8, B_);
    prep_kernel<<<g1, 256, prep_smem>>>(input, demo, Wt, Wx, Wd, bh);

    dim3 g2(T_/8, B_);
    strip_kernel<<<g2, 256>>>(input, Wa, ba, out_e, out_v);
}